// round 16
// baseline (speedup 1.0000x reference)
#include <cuda_runtime.h>
#include <cuda_fp16.h>
#include <cstdint>
#include <math.h>

#define B_GRAPHS 512
#define N_NODES  128
#define F_OUT    256
#define HEADS    4
#define HID      64
#define M_TOT    (B_GRAPHS * N_NODES)   // 65536
#define LOG2E    1.4426950408889634f

__device__ __half g_X[(size_t)M_TOT * F_OUT];
__device__ __half g_Y[(size_t)M_TOT * F_OUT];
__device__ __half g_Wt[3][256 * 256];

// ---------------------------------------------------------------------------
#define CP_ASYNC16(dst, src) \
    asm volatile("cp.async.cg.shared.global [%0], [%1], 16;" \
        :: "r"((uint32_t)(dst)), "l"(src) : "memory")
#define CP_COMMIT() asm volatile("cp.async.commit_group;" ::: "memory")
#define CP_WAIT1()  asm volatile("cp.async.wait_group 1;" ::: "memory")
#define CP_WAIT0()  asm volatile("cp.async.wait_group 0;" ::: "memory")

__device__ __forceinline__ uint32_t smem_to_u32(const void* p) {
    uint32_t a;
    asm("{ .reg .u64 t; cvta.to.shared.u64 t, %1; cvt.u32.u64 %0, t; }"
        : "=r"(a) : "l"(p));
    return a;
}

__device__ __forceinline__ float ex2(float x) {
    float r;
    asm("ex2.approx.f32 %0, %1;" : "=f"(r) : "f"(x));
    return r;
}

__device__ __forceinline__ uint32_t h2pack(float lo, float hi) {
    uint32_t d;
    asm("cvt.rn.f16x2.f32 %0, %1, %2;" : "=r"(d) : "f"(hi), "f"(lo));
    return d;
}

__device__ __forceinline__ void ldsm_x4(
    uint32_t& r0, uint32_t& r1, uint32_t& r2, uint32_t& r3, uint32_t addr)
{
    asm volatile("ldmatrix.sync.aligned.m8n8.x4.shared.b16 {%0,%1,%2,%3}, [%4];"
        : "=r"(r0), "=r"(r1), "=r"(r2), "=r"(r3) : "r"(addr));
}

__device__ __forceinline__ void ldsm_x4_trans(
    uint32_t& r0, uint32_t& r1, uint32_t& r2, uint32_t& r3, uint32_t addr)
{
    asm volatile(
        "ldmatrix.sync.aligned.m8n8.x4.trans.shared.b16 {%0,%1,%2,%3}, [%4];"
        : "=r"(r0), "=r"(r1), "=r"(r2), "=r"(r3) : "r"(addr));
}

__device__ __forceinline__ void mma_f16(
    float& d0, float& d1, float& d2, float& d3,
    uint32_t a0, uint32_t a1, uint32_t a2, uint32_t a3,
    uint32_t b0, uint32_t b1)
{
    asm volatile(
        "mma.sync.aligned.m16n8k16.row.col.f32.f16.f16.f32 "
        "{%0,%1,%2,%3}, {%4,%5,%6,%7}, {%8,%9}, {%0,%1,%2,%3};"
        : "+f"(d0), "+f"(d1), "+f"(d2), "+f"(d3)
        : "r"(a0), "r"(a1), "r"(a2), "r"(a3), "r"(b0), "r"(b1));
}

__device__ __forceinline__ float leaky(float a) {
    return fmaxf(a, 0.2f * a);
}

// ---------------------------------------------------------------------------
__global__ __launch_bounds__(256) void round_x_kernel(
    const float* __restrict__ x, __half* __restrict__ xr)
{
    int t = blockIdx.x * 256 + threadIdx.x;
    float4 v = ((const float4*)x)[t];
    __half2* o = (__half2*)xr;
    o[t * 2]     = __floats2half2_rn(v.x, v.y);
    o[t * 2 + 1] = __floats2half2_rn(v.z, v.w);
}

__global__ __launch_bounds__(256) void transpose_all_kernel(
    const float* __restrict__ W0, const float* __restrict__ W1,
    const float* __restrict__ W2, __half* __restrict__ Wt)
{
    int t = blockIdx.x * 256 + threadIdx.x;
    if (t < 128 * 256) {
        int k = t >> 8, n = t & 255;
        Wt[(size_t)n * 128 + k] = __float2half_rn(W0[t]);
    } else if (t < 128 * 256 + 256 * 256) {
        int t2 = t - 128 * 256;
        int k = t2 >> 8, n = t2 & 255;
        Wt[65536 + (size_t)n * 256 + k] = __float2half_rn(W1[t2]);
    } else {
        int t3 = t - 128 * 256 - 256 * 256;
        int k = t3 >> 8, n = t3 & 255;
        Wt[131072 + (size_t)n * 256 + k] = __float2half_rn(W2[t3]);
    }
}

// ===========================================================================
// Fused layer kernel, fp16 MMA, 512 thr, 2 CTAs/SM.
// H stored ROW-MAJOR [j][n] with 256B-row XOR swizzle; attention B-fragments
// via ldmatrix.trans (no software transpose, half2 epilogue stores).
// ===========================================================================
#define OFF_SVP  3072                 // [4][128] f32 partials
#define OFF_DVP  5120
#define OFF_SV   7168                 // [2][128] f32 scaled scores
#define OFF_DV   8192
#define OFF_SMX  9216                 // [2]
#define OFF_QV   9472                 // [2][128]
#define OFF_U    10496                // 128B aligned
#define A_STG    16384                // 128 rows x 128B, SW-swizzled
#define OFF_BSTG (OFF_U + 3 * A_STG)  // B stages after 3 A stages
#define OFF_QP   (OFF_U + 32768)      // [16][128] f32, after H, in dead stages
#define LAYER_SMEM (OFF_U + 6 * A_STG)   // 108800 -> 2 CTAs/SM
// H: 128 rows x 256B (swizzled) = 32768 B, overlaps A stages (dead in attn).

__global__ __launch_bounds__(512, 2) void layer_kernel(
    const __half* __restrict__ A, const __half* __restrict__ Wt,
    const float* __restrict__ att_src, const float* __restrict__ att_dst,
    const float* __restrict__ bias_g,
    __half* __restrict__ X, float* __restrict__ out_final,
    int K, int last)
{
    extern __shared__ char sm[];
    uint32_t sb = smem_to_u32(sm);
    float* atts  = (float*)(sm);
    float* attd  = (float*)(sm + 1024);
    float* biass = (float*)(sm + 2048);
    float* svp   = (float*)(sm + OFF_SVP);
    float* dvp   = (float*)(sm + OFF_DVP);
    float* sv    = (float*)(sm + OFF_SV);
    float* dv    = (float*)(sm + OFF_DV);
    float* smaxs = (float*)(sm + OFF_SMX);
    float* qv    = (float*)(sm + OFF_QV);
    float* qpart = (float*)(sm + OFF_QP);

    const int tid = threadIdx.x;
    const int warp = tid >> 5, lane = tid & 31;
    const int gid = lane >> 2, tig = lane & 3;
    const int wm = warp & 3, wn = warp >> 2;
    const int b = blockIdx.x, m0 = b * 128;
    const int t4 = lane >> 3, r8 = lane & 7;

    if (tid < 256) {
        atts[tid]  = att_src[tid];
        attd[tid]  = att_dst[tid];
        biass[tid] = bias_g[tid];
    }

    // GEMM fragment row bases (SW staging: 128B rows, chunk ^= r8)
    const uint32_t abase0 = (uint32_t)((wm * 32 + (t4 & 1) * 8 + r8) * 128);
    const uint32_t bbase0 = (uint32_t)((wn * 32 + (t4 >> 1) * 8 + r8) * 128);
    const int cbA = t4 >> 1, cbB = t4 & 1;

    // attention: warp = (hl head, wm8 row-group); 16 rows x 64 cols
    const int wm8 = warp & 7, hl = warp >> 3;
    // trans-LDSM per-lane base into H (row-major, 256B rows, swizzled):
    //   j_lane = (t4&1)*8 + r8 (plus kk*16), chunk-xor index base cbH = t4>>1
    const uint32_t hbase = (uint32_t)(((t4 & 1) * 8 + r8) * 256);
    const int cbH = t4 >> 1;

    const int NC = K >> 6;     // chunks of 64 k

#pragma unroll 1
    for (int nh = 0; nh < 2; nh++) {
        // ---------------- GEMM half: 128 x 128 (fp16) ----------------
        float acc[2][4][4];
#pragma unroll
        for (int mt = 0; mt < 2; mt++)
#pragma unroll
            for (int nt = 0; nt < 4; nt++)
#pragma unroll
                for (int c = 0; c < 4; c++) acc[mt][nt][c] = 0.f;

        auto load_chunk = [&](int k0, int stage) {
            uint32_t ab = sb + OFF_U + stage * A_STG;
            uint32_t bb = sb + OFF_BSTG + stage * A_STG;
#pragma unroll
            for (int i = 0; i < 2; i++) {
                int g = tid + i * 512;
                int row = g >> 3, c = g & 7;
                uint32_t doff = (uint32_t)(row * 128 + ((c ^ (row & 7)) << 4));
                CP_ASYNC16(ab + doff,
                           A + (size_t)(m0 + row) * K + k0 + c * 8);
            }
#pragma unroll
            for (int i = 0; i < 2; i++) {
                int g = tid + i * 512;
                int row = g >> 3, c = g & 7;
                uint32_t doff = (uint32_t)(row * 128 + ((c ^ (row & 7)) << 4));
                CP_ASYNC16(bb + doff,
                           Wt + (size_t)(nh * 128 + row) * K + k0 + c * 8);
            }
        };

        load_chunk(0, 0);
        CP_COMMIT();
        if (NC > 1) { load_chunk(64, 1); CP_COMMIT(); }

        for (int c = 0; c < NC; c++) {
            if (c + 1 < NC) CP_WAIT1(); else CP_WAIT0();
            __syncthreads();
            if (c + 2 < NC) {
                load_chunk((c + 2) << 6, (c + 2) % 3);
                CP_COMMIT();
            }

            uint32_t as_b = sb + OFF_U + (c % 3) * A_STG;
            uint32_t bs_b = sb + OFF_BSTG + (c % 3) * A_STG;
#pragma unroll
            for (int kk = 0; kk < 4; kk++) {
                uint32_t offA = (uint32_t)((((kk << 1) | cbA) ^ r8) << 4);
                uint32_t offB = (uint32_t)((((kk << 1) | cbB) ^ r8) << 4);
                uint32_t a[2][4];
#pragma unroll
                for (int mt = 0; mt < 2; mt++)
                    ldsm_x4(a[mt][0], a[mt][1], a[mt][2], a[mt][3],
                            as_b + abase0 + mt * 2048 + offA);
                uint32_t bf[4][2];
#pragma unroll
                for (int pr = 0; pr < 2; pr++)
                    ldsm_x4(bf[pr * 2][0], bf[pr * 2][1],
                            bf[pr * 2 + 1][0], bf[pr * 2 + 1][1],
                            bs_b + bbase0 + pr * 2048 + offB);
#pragma unroll
                for (int mt = 0; mt < 2; mt++)
#pragma unroll
                    for (int nt = 0; nt < 4; nt++)
                        mma_f16(acc[mt][nt][0], acc[mt][nt][1],
                                acc[mt][nt][2], acc[mt][nt][3],
                                a[mt][0], a[mt][1], a[mt][2], a[mt][3],
                                bf[nt][0], bf[nt][1]);
            }
        }
        __syncthreads();   // stage reads done before H overwrites U

        // ------ epilogue: H row-major (swizzled, half2 stores) + scores -----
        const int hl_w = wn >> 1;
        const int wchunk = (wn & 1) * 4;    // chunk base within head-half
#pragma unroll
        for (int mt = 0; mt < 2; mt++) {
#pragma unroll
            for (int h2 = 0; h2 < 2; h2++) {
                int rl = wm * 32 + mt * 16 + gid + 8 * h2;
                float s = 0.f, d = 0.f;
                uint32_t rowb = (uint32_t)(rl * 256 + hl_w * 128) + (tig * 4);
                int rx = rl & 7;
#pragma unroll
                for (int nt = 0; nt < 4; nt++) {
                    int gc = nh * 128 + wn * 32 + nt * 8 + tig * 2;
                    float v0 = acc[mt][nt][h2 * 2], v1 = acc[mt][nt][h2 * 2 + 1];
                    s = fmaf(v0, atts[gc], s);  s = fmaf(v1, atts[gc + 1], s);
                    d = fmaf(v0, attd[gc], d);  d = fmaf(v1, attd[gc + 1], d);
                    uint32_t byte = rowb + (uint32_t)(((wchunk + nt) ^ rx) << 4);
                    *(__half2*)(sm + OFF_U + byte) = __floats2half2_rn(v0, v1);
                }
                s += __shfl_xor_sync(0xffffffffu, s, 1);
                s += __shfl_xor_sync(0xffffffffu, s, 2);
                d += __shfl_xor_sync(0xffffffffu, d, 1);
                d += __shfl_xor_sync(0xffffffffu, d, 2);
                if (tig == 0) {
                    svp[wn * 128 + rl] = s;
                    dvp[wn * 128 + rl] = d;
                }
            }
        }
        __syncthreads();

        // reduce partials (scaled by log2e) -> sv / dv / smaxs
        if (tid < 256) {
            int hh = tid >> 7, j = tid & 127;
            sv[hh * 128 + j] = (svp[(2 * hh) * 128 + j]
                                + svp[(2 * hh + 1) * 128 + j]) * LOG2E;
            dv[hh * 128 + j] = (dvp[(2 * hh) * 128 + j]
                                + dvp[(2 * hh + 1) * 128 + j]) * LOG2E;
        } else if (tid < 320) {
            int t = tid - 256, hh = t >> 5, l = t & 31;
            float m = -1e30f;
#pragma unroll
            for (int q = 0; q < 4; q++) {
                int j = l + q * 32;
                m = fmaxf(m, svp[(2 * hh) * 128 + j]
                             + svp[(2 * hh + 1) * 128 + j]);
            }
#pragma unroll
            for (int off = 16; off; off >>= 1)
                m = fmaxf(m, __shfl_xor_sync(0xffffffffu, m, off));
            if (l == 0) smaxs[hh] = m * LOG2E;
        }
        __syncthreads();

        // ---------------- attention: 16x64 warp tiles, trans-LDSM ----------
        {
            const int gh = nh * 2 + hl;
            const uint32_t ht_b = sb + OFF_U + (uint32_t)(hl * 128) + hbase;
            const float* svh = sv + hl * 128;

            const int rr0 = wm8 * 16 + gid;
            const float dd0 = dv[hl * 128 + rr0];
            const float dd1 = dv[hl * 128 + rr0 + 8];
            const float smx = smaxs[hl];
            const float mx0 = leaky(smx + dd0);
            const float mx1 = leaky(smx + dd1);

            if (!last) {
                float oacc[8][4];
#pragma unroll
                for (int nt = 0; nt < 8; nt++)
#pragma unroll
                    for (int c = 0; c < 4; c++) oacc[nt][c] = 0.f;
                float sum0 = 0.f, sum1 = 0.f;

#pragma unroll
                for (int kk = 0; kk < 8; kk++) {
                    float2 sjA = *(const float2*)&svh[kk * 16 + tig * 2];
                    float2 sjB = *(const float2*)&svh[kk * 16 + tig * 2 + 8];
                    float p00 = ex2(leaky(sjA.x + dd0) - mx0);
                    float p01 = ex2(leaky(sjA.y + dd0) - mx0);
                    float p10 = ex2(leaky(sjA.x + dd1) - mx1);
                    float p11 = ex2(leaky(sjA.y + dd1) - mx1);
                    float p02 = ex2(leaky(sjB.x + dd0) - mx0);
                    float p03 = ex2(leaky(sjB.y + dd0) - mx0);
                    float p12 = ex2(leaky(sjB.x + dd1) - mx1);
                    float p13 = ex2(leaky(sjB.y + dd1) - mx1);
                    sum0 += p00 + p01 + p02 + p03;
                    sum1 += p10 + p11 + p12 + p13;
                    uint32_t a0 = h2pack(p00, p01);
                    uint32_t a1 = h2pack(p10, p11);
                    uint32_t a2 = h2pack(p02, p03);
                    uint32_t a3 = h2pack(p12, p13);
                    uint32_t kb = ht_b + (uint32_t)(kk * 4096);
#pragma unroll
                    for (int pr = 0; pr < 4; pr++) {
                        uint32_t b0, b1, b2, b3;
                        ldsm_x4_trans(b0, b1, b2, b3,
                                      kb + (uint32_t)((((pr << 1) | cbH) ^ r8) << 4));
                        mma_f16(oacc[pr * 2][0], oacc[pr * 2][1],
                                oacc[pr * 2][2], oacc[pr * 2][3],
                                a0, a1, a2, a3, b0, b1);
                        mma_f16(oacc[pr * 2 + 1][0], oacc[pr * 2 + 1][1],
                                oacc[pr * 2 + 1][2], oacc[pr * 2 + 1][3],
                                a0, a1, a2, a3, b2, b3);
                    }
                }
                sum0 += __shfl_xor_sync(0xffffffffu, sum0, 1);
                sum0 += __shfl_xor_sync(0xffffffffu, sum0, 2);
                sum1 += __shfl_xor_sync(0xffffffffu, sum1, 1);
                sum1 += __shfl_xor_sync(0xffffffffu, sum1, 2);
                float inv0 = 1.0f / sum0, inv1 = 1.0f / sum1;

                __half* o0 = X + ((size_t)m0 + rr0) * 256 + gh * 64;
                __half* o1 = X + ((size_t)m0 + rr0 + 8) * 256 + gh * 64;
#pragma unroll
                for (int nt = 0; nt < 8; nt++) {
                    int col = nt * 8 + tig * 2;
                    float bb0 = biass[gh * 64 + col];
                    float bb1 = biass[gh * 64 + col + 1];
                    *(__half2*)&o0[col] = __floats2half2_rn(
                        fmaf(oacc[nt][0], inv0, bb0),
                        fmaf(oacc[nt][1], inv0, bb1));
                    *(__half2*)&o1[col] = __floats2half2_rn(
                        fmaf(oacc[nt][2], inv1, bb0),
                        fmaf(oacc[nt][3], inv1, bb1));
                }
            } else {
                // q path: q_j = sum_i e_ij / r_i (no MMA)
                float sum0 = 0.f, sum1 = 0.f;
#pragma unroll
                for (int kk = 0; kk < 8; kk++) {
                    float2 sjA = *(const float2*)&svh[kk * 16 + tig * 2];
                    float2 sjB = *(const float2*)&svh[kk * 16 + tig * 2 + 8];
                    sum0 += ex2(leaky(sjA.x + dd0) - mx0)
                          + ex2(leaky(sjA.y + dd0) - mx0)
                          + ex2(leaky(sjB.x + dd0) - mx0)
                          + ex2(leaky(sjB.y + dd0) - mx0);
                    sum1 += ex2(leaky(sjA.x + dd1) - mx1)
                          + ex2(leaky(sjA.y + dd1) - mx1)
                          + ex2(leaky(sjB.x + dd1) - mx1)
                          + ex2(leaky(sjB.y + dd1) - mx1);
                }
                sum0 += __shfl_xor_sync(0xffffffffu, sum0, 1);
                sum0 += __shfl_xor_sync(0xffffffffu, sum0, 2);
                sum1 += __shfl_xor_sync(0xffffffffu, sum1, 1);
                sum1 += __shfl_xor_sync(0xffffffffu, sum1, 2);
                float inv0 = 1.0f / sum0, inv1 = 1.0f / sum1;

#pragma unroll
                for (int kk = 0; kk < 8; kk++) {
                    float2 sjA = *(const float2*)&svh[kk * 16 + tig * 2];
                    float2 sjB = *(const float2*)&svh[kk * 16 + tig * 2 + 8];
                    float q0 = ex2(leaky(sjA.x + dd0) - mx0) * inv0
                             + ex2(leaky(sjA.x + dd1) - mx1) * inv1;
                    float q1 = ex2(leaky(sjA.y + dd0) - mx0) * inv0
                             + ex2(leaky(sjA.y + dd1) - mx1) * inv1;
                    float q2 = ex2(leaky(sjB.x + dd0) - mx0) * inv0
                             + ex2(leaky(sjB.x + dd1) - mx1) * inv1;
                    float q3 = ex2(leaky(sjB.y + dd0) - mx0) * inv0
                             + ex2(leaky(sjB.y + dd1) - mx1) * inv1;
#pragma unroll
                    for (int off = 4; off < 32; off <<= 1) {
                        q0 += __shfl_xor_sync(0xffffffffu, q0, off);
                        q1 += __shfl_xor_sync(0xffffffffu, q1, off);
                        q2 += __shfl_xor_sync(0xffffffffu, q2, off);
                        q3 += __shfl_xor_sync(0xffffffffu, q3, off);
                    }
                    if (gid == 0) {
                        int jb = kk * 16 + tig * 2;
                        qpart[(hl * 8 + wm8) * 128 + jb]     = q0;
                        qpart[(hl * 8 + wm8) * 128 + jb + 1] = q1;
                        qpart[(hl * 8 + wm8) * 128 + jb + 8] = q2;
                        qpart[(hl * 8 + wm8) * 128 + jb + 9] = q3;
                    }
                }
            }
        }

        if (last) {
            __syncthreads();
            if (tid < 256) {
                int hh = tid >> 7, cc = tid & 127;
                float qs = 0.f;
#pragma unroll
                for (int w = 0; w < 8; w++)
                    qs += qpart[(hh * 8 + w) * 128 + cc];
                qv[hh * 128 + cc] = qs;
            }
            __syncthreads();
#pragma unroll 1
            for (int hq = 0; hq < 2; hq++) {
                int c = tid >> 3, t8 = tid & 7;
                float a3 = 0.f;
#pragma unroll 4
                for (int jj = 0; jj < 16; jj++) {
                    int j = t8 * 16 + jj;
                    uint32_t byte = (uint32_t)(j * 256 + hq * 128
                                  + (((c >> 3) ^ (j & 7)) << 4) + (c & 7) * 2);
                    a3 += qv[hq * 128 + j] *
                          __half2float(*(const __half*)(sm + OFF_U + byte));
                }
                a3 += __shfl_xor_sync(0xffffffffu, a3, 1);
                a3 += __shfl_xor_sync(0xffffffffu, a3, 2);
                a3 += __shfl_xor_sync(0xffffffffu, a3, 4);
                int gho = nh * 2 + hq;
                if (t8 == 0)
                    out_final[(size_t)b * 256 + gho * 64 + c] =
                        a3 + 128.f * biass[gho * 64 + c];
            }
        }
        __syncthreads();   // H dead; next half may overwrite staging
    } // nh
}

// ---------------------------------------------------------------------------
extern "C" void kernel_launch(void* const* d_in, const int* in_sizes, int n_in,
                              void* d_out, int out_size)
{
    const float* x = (const float*)d_in[0];
    const float* W[3]    = {(const float*)d_in[2], (const float*)d_in[6],  (const float*)d_in[10]};
    const float* asv[3]  = {(const float*)d_in[3], (const float*)d_in[7],  (const float*)d_in[11]};
    const float* adv[3]  = {(const float*)d_in[4], (const float*)d_in[8],  (const float*)d_in[12]};
    const float* bias[3] = {(const float*)d_in[5], (const float*)d_in[9],  (const float*)d_in[13]};

    __half *pX, *pY, *pWt;
    cudaGetSymbolAddress((void**)&pX, g_X);
    cudaGetSymbolAddress((void**)&pY, g_Y);
    cudaGetSymbolAddress((void**)&pWt, g_Wt);

    cudaFuncSetAttribute(layer_kernel,
                         cudaFuncAttributeMaxDynamicSharedMemorySize, LAYER_SMEM);

    transpose_all_kernel<<<640, 256>>>(W[0], W[1], W[2], pWt);
    round_x_kernel<<<8192, 256>>>(x, pY);

    // layer 0: g_Y(xr) -> g_X ; layer 1: g_X -> g_Y ; layer 2: g_Y -> d_out
    const __half* in_buf[3]  = {pY, pX, pY};
    __half*       out_buf[3] = {pX, pY, nullptr};

    for (int l = 0; l < 3; l++) {
        const int K = (l == 0) ? 128 : 256;
        const __half* Wtl = pWt + (size_t)l * 65536;
        layer_kernel<<<512, 512, LAYER_SMEM>>>(
            in_buf[l], Wtl, asv[l], adv[l], bias[l],
            out_buf[l], (float*)d_out, K, l == 2);
    }
}

// round 17
// speedup vs baseline: 1.2199x; 1.2199x over previous
#include <cuda_runtime.h>
#include <cuda_fp16.h>
#include <cstdint>
#include <math.h>

#define B_GRAPHS 512
#define N_NODES  128
#define F_OUT    256
#define HEADS    4
#define HID      64
#define M_TOT    (B_GRAPHS * N_NODES)   // 65536
#define LOG2E    1.4426950408889634f

__device__ __half g_X[(size_t)M_TOT * F_OUT];
__device__ __half g_Y[(size_t)M_TOT * F_OUT];
__device__ __half g_Wt[3][256 * 256];

// ---------------------------------------------------------------------------
#define CP_ASYNC16(dst, src) \
    asm volatile("cp.async.cg.shared.global [%0], [%1], 16;" \
        :: "r"((uint32_t)(dst)), "l"(src) : "memory")
#define CP_COMMIT() asm volatile("cp.async.commit_group;" ::: "memory")
#define CP_WAIT0()  asm volatile("cp.async.wait_group 0;" ::: "memory")

__device__ __forceinline__ uint32_t smem_to_u32(const void* p) {
    uint32_t a;
    asm("{ .reg .u64 t; cvta.to.shared.u64 t, %1; cvt.u32.u64 %0, t; }"
        : "=r"(a) : "l"(p));
    return a;
}

__device__ __forceinline__ float ex2(float x) {
    float r;
    asm("ex2.approx.f32 %0, %1;" : "=f"(r) : "f"(x));
    return r;
}

__device__ __forceinline__ uint32_t h2pack(float lo, float hi) {
    uint32_t d;
    asm("cvt.rn.f16x2.f32 %0, %1, %2;" : "=r"(d) : "f"(hi), "f"(lo));
    return d;
}

__device__ __forceinline__ void ldsm_x4(
    uint32_t& r0, uint32_t& r1, uint32_t& r2, uint32_t& r3, uint32_t addr)
{
    asm volatile("ldmatrix.sync.aligned.m8n8.x4.shared.b16 {%0,%1,%2,%3}, [%4];"
        : "=r"(r0), "=r"(r1), "=r"(r2), "=r"(r3) : "r"(addr));
}

__device__ __forceinline__ void ldsm_x4_trans(
    uint32_t& r0, uint32_t& r1, uint32_t& r2, uint32_t& r3, uint32_t addr)
{
    asm volatile(
        "ldmatrix.sync.aligned.m8n8.x4.trans.shared.b16 {%0,%1,%2,%3}, [%4];"
        : "=r"(r0), "=r"(r1), "=r"(r2), "=r"(r3) : "r"(addr));
}

__device__ __forceinline__ void mma_f16(
    float& d0, float& d1, float& d2, float& d3,
    uint32_t a0, uint32_t a1, uint32_t a2, uint32_t a3,
    uint32_t b0, uint32_t b1)
{
    asm volatile(
        "mma.sync.aligned.m16n8k16.row.col.f32.f16.f16.f32 "
        "{%0,%1,%2,%3}, {%4,%5,%6,%7}, {%8,%9}, {%0,%1,%2,%3};"
        : "+f"(d0), "+f"(d1), "+f"(d2), "+f"(d3)
        : "r"(a0), "r"(a1), "r"(a2), "r"(a3), "r"(b0), "r"(b1));
}

__device__ __forceinline__ float leaky(float a) {
    return fmaxf(a, 0.2f * a);
}

// ---------------------------------------------------------------------------
__global__ __launch_bounds__(256) void round_x_kernel(
    const float* __restrict__ x, __half* __restrict__ xr)
{
    int t = blockIdx.x * 256 + threadIdx.x;
    float4 v = ((const float4*)x)[t];
    __half2* o = (__half2*)xr;
    o[t * 2]     = __floats2half2_rn(v.x, v.y);
    o[t * 2 + 1] = __floats2half2_rn(v.z, v.w);
}

__global__ __launch_bounds__(256) void transpose_all_kernel(
    const float* __restrict__ W0, const float* __restrict__ W1,
    const float* __restrict__ W2, __half* __restrict__ Wt)
{
    int t = blockIdx.x * 256 + threadIdx.x;
    if (t < 128 * 256) {
        int k = t >> 8, n = t & 255;
        Wt[(size_t)n * 128 + k] = __float2half_rn(W0[t]);
    } else if (t < 128 * 256 + 256 * 256) {
        int t2 = t - 128 * 256;
        int k = t2 >> 8, n = t2 & 255;
        Wt[65536 + (size_t)n * 256 + k] = __float2half_rn(W1[t2]);
    } else {
        int t3 = t - 128 * 256 - 256 * 256;
        int k = t3 >> 8, n = t3 & 255;
        Wt[131072 + (size_t)n * 256 + k] = __float2half_rn(W2[t3]);
    }
}

// ===========================================================================
// Per-(graph, head) layer kernel: 256 thr, 8 warps, 4 CTAs/SM.
//   GEMM 128x64 (K<=256), fp16 mma, 2-stage single-barrier cp.async pipeline.
//   H [128 rows][64 cols] fp16 row-major (128B swizzled rows) in smem.
//   Attention: register softmax -> A frags; B frags via ldmatrix.trans on H.
// ===========================================================================
#define OFF_ATTS 0                    // [64] f32
#define OFF_ATTD 256
#define OFF_BIAS 512
#define OFF_SVP  768                  // [2][128] f32 partials
#define OFF_DVP  1792
#define OFF_SV   2816                 // [128] f32 scaled
#define OFF_DV   3328
#define OFF_SMX  3840
#define OFF_U    3968                 // 128B aligned
#define A_STG    16384                // 128 rows x 128B swizzled
#define B_STG    8192                 // 64 rows x 128B swizzled
#define OFF_BSTG (OFF_U + 2 * A_STG)
#define OFF_QP   (OFF_U + 16384)      // [8][128] f32 (in dead stage A1)
#define OFF_QV   (OFF_U + 20480)      // [128] f32
#define LAYER_SMEM (OFF_BSTG + 2 * B_STG - 0)   // 3968+49152 = 53120 -> 4/SM
// H: 128 rows x 128B = 16384 B at OFF_U (stages dead when H live).

__global__ __launch_bounds__(256, 4) void layer_kernel(
    const __half* __restrict__ A, const __half* __restrict__ Wt,
    const float* __restrict__ att_src, const float* __restrict__ att_dst,
    const float* __restrict__ bias_g,
    __half* __restrict__ X, float* __restrict__ out_final,
    int K, int last)
{
    extern __shared__ char sm[];
    uint32_t sb = smem_to_u32(sm);
    float* atts  = (float*)(sm + OFF_ATTS);
    float* attd  = (float*)(sm + OFF_ATTD);
    float* biass = (float*)(sm + OFF_BIAS);
    float* svp   = (float*)(sm + OFF_SVP);
    float* dvp   = (float*)(sm + OFF_DVP);
    float* sv    = (float*)(sm + OFF_SV);
    float* dv    = (float*)(sm + OFF_DV);
    float* smaxs = (float*)(sm + OFF_SMX);
    float* qpart = (float*)(sm + OFF_QP);
    float* qv    = (float*)(sm + OFF_QV);

    const int tid = threadIdx.x;
    const int warp = tid >> 5, lane = tid & 31;
    const int gid = lane >> 2, tig = lane & 3;
    const int wm = warp & 3, wn = warp >> 2;      // GEMM: 4 row-grps x 2 col-grps
    const int b = blockIdx.x, gh = blockIdx.y;
    const int m0 = b * 128;
    const int t4 = lane >> 3, r8 = lane & 7;

    if (tid < 64) {
        atts[tid]  = att_src[gh * 64 + tid];
        attd[tid]  = att_dst[gh * 64 + tid];
        biass[tid] = bias_g[gh * 64 + tid];
    }

    // GEMM ldmatrix bases (128B swizzled rows)
    const uint32_t abase0 = (uint32_t)((wm * 32 + (t4 & 1) * 8 + r8) * 128);
    const uint32_t bbase0 = (uint32_t)((wn * 32 + (t4 >> 1) * 8 + r8) * 128);
    const int cbA = t4 >> 1, cbB = t4 & 1;
    // attention trans-LDSM base into H
    const uint32_t hbase = (uint32_t)(((t4 & 1) * 8 + r8) * 128);
    const int cbH = t4 >> 1;

    const int NC = K >> 6;     // chunks of 64 k

    // ---------------- GEMM: H(128x64) = A(128xK) @ Wt(gh)^T ----------------
    float acc[2][4][4];
#pragma unroll
    for (int mt = 0; mt < 2; mt++)
#pragma unroll
        for (int nt = 0; nt < 4; nt++)
#pragma unroll
            for (int c = 0; c < 4; c++) acc[mt][nt][c] = 0.f;

    auto load_chunk = [&](int k0, int stage) {
        uint32_t ab = sb + OFF_U + stage * A_STG;
        uint32_t bb = sb + OFF_BSTG + stage * B_STG;
#pragma unroll
        for (int i = 0; i < 4; i++) {          // A: 128 rows x 8 chunks
            int g = tid + i * 256;
            int row = g >> 3, c = g & 7;
            uint32_t doff = (uint32_t)(row * 128 + ((c ^ (row & 7)) << 4));
            CP_ASYNC16(ab + doff, A + (size_t)(m0 + row) * K + k0 + c * 8);
        }
#pragma unroll
        for (int i = 0; i < 2; i++) {          // B: 64 rows x 8 chunks
            int g = tid + i * 256;
            int row = g >> 3, c = g & 7;
            uint32_t doff = (uint32_t)(row * 128 + ((c ^ (row & 7)) << 4));
            CP_ASYNC16(bb + doff,
                       Wt + (size_t)(gh * 64 + row) * K + k0 + c * 8);
        }
    };

    load_chunk(0, 0);
    CP_COMMIT();

    // 2-stage single-barrier pipeline (proven R14):
    //   WAIT0 -> barrier -> issue loads(c+1, s^1) -> MMA(stage s)
    for (int c = 0; c < NC; c++) {
        CP_WAIT0();
        __syncthreads();
        if (c + 1 < NC) {
            load_chunk((c + 1) << 6, (c + 1) & 1);
            CP_COMMIT();
        }

        uint32_t as_b = sb + OFF_U + (c & 1) * A_STG;
        uint32_t bs_b = sb + OFF_BSTG + (c & 1) * B_STG;
#pragma unroll
        for (int kk = 0; kk < 4; kk++) {
            uint32_t offA = (uint32_t)((((kk << 1) | cbA) ^ r8) << 4);
            uint32_t offB = (uint32_t)((((kk << 1) | cbB) ^ r8) << 4);
            uint32_t a[2][4];
#pragma unroll
            for (int mt = 0; mt < 2; mt++)
                ldsm_x4(a[mt][0], a[mt][1], a[mt][2], a[mt][3],
                        as_b + abase0 + mt * 2048 + offA);
            uint32_t bf[4][2];
#pragma unroll
            for (int pr = 0; pr < 2; pr++)
                ldsm_x4(bf[pr * 2][0], bf[pr * 2][1],
                        bf[pr * 2 + 1][0], bf[pr * 2 + 1][1],
                        bs_b + bbase0 + pr * 2048 + offB);
#pragma unroll
            for (int mt = 0; mt < 2; mt++)
#pragma unroll
                for (int nt = 0; nt < 4; nt++)
                    mma_f16(acc[mt][nt][0], acc[mt][nt][1],
                            acc[mt][nt][2], acc[mt][nt][3],
                            a[mt][0], a[mt][1], a[mt][2], a[mt][3],
                            bf[nt][0], bf[nt][1]);
        }
    }
    __syncthreads();   // stage reads done before H overwrites U

    // ------- epilogue: H row-major (swizzled half2 stores) + scores --------
#pragma unroll
    for (int mt = 0; mt < 2; mt++) {
#pragma unroll
        for (int h2 = 0; h2 < 2; h2++) {
            int rl = wm * 32 + mt * 16 + gid + 8 * h2;
            float s = 0.f, d = 0.f;
            int rx = rl & 7;
            uint32_t rowb = (uint32_t)(rl * 128) + tig * 4;
#pragma unroll
            for (int nt = 0; nt < 4; nt++) {
                int cl = wn * 32 + nt * 8 + tig * 2;
                float v0 = acc[mt][nt][h2 * 2], v1 = acc[mt][nt][h2 * 2 + 1];
                s = fmaf(v0, atts[cl], s);  s = fmaf(v1, atts[cl + 1], s);
                d = fmaf(v0, attd[cl], d);  d = fmaf(v1, attd[cl + 1], d);
                uint32_t byte = rowb + (uint32_t)(((wn * 4 + nt) ^ rx) << 4);
                *(__half2*)(sm + OFF_U + byte) = __floats2half2_rn(v0, v1);
            }
            s += __shfl_xor_sync(0xffffffffu, s, 1);
            s += __shfl_xor_sync(0xffffffffu, s, 2);
            d += __shfl_xor_sync(0xffffffffu, d, 1);
            d += __shfl_xor_sync(0xffffffffu, d, 2);
            if (tig == 0) {
                svp[wn * 128 + rl] = s;
                dvp[wn * 128 + rl] = d;
            }
        }
    }
    __syncthreads();

    // reduce partials (scaled by log2e) -> sv / dv ; head score max -> smaxs
    if (tid < 128) {
        sv[tid] = (svp[tid] + svp[128 + tid]) * LOG2E;
        dv[tid] = (dvp[tid] + dvp[128 + tid]) * LOG2E;
    } else if (tid < 160) {
        int l = tid - 128;
        float m = -1e30f;
#pragma unroll
        for (int q = 0; q < 4; q++) {
            int j = l + q * 32;
            m = fmaxf(m, svp[j] + svp[128 + j]);
        }
#pragma unroll
        for (int off = 16; off; off >>= 1)
            m = fmaxf(m, __shfl_xor_sync(0xffffffffu, m, off));
        if (l == 0) smaxs[0] = m * LOG2E;
    }
    __syncthreads();

    // ---------------- attention: warp = 16-row group, 64 cols --------------
    {
        const int rr0 = warp * 16 + gid;
        const float dd0 = dv[rr0];
        const float dd1 = dv[rr0 + 8];
        const float smx = smaxs[0];
        const float mx0 = leaky(smx + dd0);   // exact row max (monotone)
        const float mx1 = leaky(smx + dd1);

        if (!last) {
            float oacc[8][4];
#pragma unroll
            for (int nt = 0; nt < 8; nt++)
#pragma unroll
                for (int c = 0; c < 4; c++) oacc[nt][c] = 0.f;
            float sum0 = 0.f, sum1 = 0.f;

#pragma unroll
            for (int kk = 0; kk < 8; kk++) {
                float2 sjA = *(const float2*)&sv[kk * 16 + tig * 2];
                float2 sjB = *(const float2*)&sv[kk * 16 + tig * 2 + 8];
                float p00 = ex2(leaky(sjA.x + dd0) - mx0);
                float p01 = ex2(leaky(sjA.y + dd0) - mx0);
                float p10 = ex2(leaky(sjA.x + dd1) - mx1);
                float p11 = ex2(leaky(sjA.y + dd1) - mx1);
                float p02 = ex2(leaky(sjB.x + dd0) - mx0);
                float p03 = ex2(leaky(sjB.y + dd0) - mx0);
                float p12 = ex2(leaky(sjB.x + dd1) - mx1);
                float p13 = ex2(leaky(sjB.y + dd1) - mx1);
                sum0 += p00 + p01 + p02 + p03;
                sum1 += p10 + p11 + p12 + p13;
                uint32_t a0 = h2pack(p00, p01);
                uint32_t a1 = h2pack(p10, p11);
                uint32_t a2 = h2pack(p02, p03);
                uint32_t a3 = h2pack(p12, p13);
                uint32_t kb = sb + OFF_U + hbase + (uint32_t)(kk * 2048);
#pragma unroll
                for (int pr = 0; pr < 4; pr++) {
                    uint32_t b0, b1, b2, b3;
                    ldsm_x4_trans(b0, b1, b2, b3,
                                  kb + (uint32_t)((((pr << 1) | cbH) ^ r8) << 4));
                    mma_f16(oacc[pr * 2][0], oacc[pr * 2][1],
                            oacc[pr * 2][2], oacc[pr * 2][3],
                            a0, a1, a2, a3, b0, b1);
                    mma_f16(oacc[pr * 2 + 1][0], oacc[pr * 2 + 1][1],
                            oacc[pr * 2 + 1][2], oacc[pr * 2 + 1][3],
                            a0, a1, a2, a3, b2, b3);
                }
            }
            sum0 += __shfl_xor_sync(0xffffffffu, sum0, 1);
            sum0 += __shfl_xor_sync(0xffffffffu, sum0, 2);
            sum1 += __shfl_xor_sync(0xffffffffu, sum1, 1);
            sum1 += __shfl_xor_sync(0xffffffffu, sum1, 2);
            float inv0 = 1.0f / sum0, inv1 = 1.0f / sum1;

            __half* o0 = X + ((size_t)m0 + rr0) * 256 + gh * 64;
            __half* o1 = X + ((size_t)m0 + rr0 + 8) * 256 + gh * 64;
#pragma unroll
            for (int nt = 0; nt < 8; nt++) {
                int col = nt * 8 + tig * 2;
                float bb0 = biass[col];
                float bb1 = biass[col + 1];
                *(__half2*)&o0[col] = __floats2half2_rn(
                    fmaf(oacc[nt][0], inv0, bb0),
                    fmaf(oacc[nt][1], inv0, bb1));
                *(__half2*)&o1[col] = __floats2half2_rn(
                    fmaf(oacc[nt][2], inv1, bb0),
                    fmaf(oacc[nt][3], inv1, bb1));
            }
        } else {
            // q path: q_j = sum_i e_ij / r_i (no MMA)
            float sum0 = 0.f, sum1 = 0.f;
#pragma unroll
            for (int kk = 0; kk < 8; kk++) {
                float2 sjA = *(const float2*)&sv[kk * 16 + tig * 2];
                float2 sjB = *(const float2*)&sv[kk * 16 + tig * 2 + 8];
                sum0 += ex2(leaky(sjA.x + dd0) - mx0)
                      + ex2(leaky(sjA.y + dd0) - mx0)
                      + ex2(leaky(sjB.x + dd0) - mx0)
                      + ex2(leaky(sjB.y + dd0) - mx0);
                sum1 += ex2(leaky(sjA.x + dd1) - mx1)
                      + ex2(leaky(sjA.y + dd1) - mx1)
                      + ex2(leaky(sjB.x + dd1) - mx1)
                      + ex2(leaky(sjB.y + dd1) - mx1);
            }
            sum0 += __shfl_xor_sync(0xffffffffu, sum0, 1);
            sum0 += __shfl_xor_sync(0xffffffffu, sum0, 2);
            sum1 += __shfl_xor_sync(0xffffffffu, sum1, 1);
            sum1 += __shfl_xor_sync(0xffffffffu, sum1, 2);
            float inv0 = 1.0f / sum0, inv1 = 1.0f / sum1;

#pragma unroll
            for (int kk = 0; kk < 8; kk++) {
                float2 sjA = *(const float2*)&sv[kk * 16 + tig * 2];
                float2 sjB = *(const float2*)&sv[kk * 16 + tig * 2 + 8];
                float q0 = ex2(leaky(sjA.x + dd0) - mx0) * inv0
                         + ex2(leaky(sjA.x + dd1) - mx1) * inv1;
                float q1 = ex2(leaky(sjA.y + dd0) - mx0) * inv0
                         + ex2(leaky(sjA.y + dd1) - mx1) * inv1;
                float q2 = ex2(leaky(sjB.x + dd0) - mx0) * inv0
                         + ex2(leaky(sjB.x + dd1) - mx1) * inv1;
                float q3 = ex2(leaky(sjB.y + dd0) - mx0) * inv0
                         + ex2(leaky(sjB.y + dd1) - mx1) * inv1;
#pragma unroll
                for (int off = 4; off < 32; off <<= 1) {
                    q0 += __shfl_xor_sync(0xffffffffu, q0, off);
                    q1 += __shfl_xor_sync(0xffffffffu, q1, off);
                    q2 += __shfl_xor_sync(0xffffffffu, q2, off);
                    q3 += __shfl_xor_sync(0xffffffffu, q3, off);
                }
                if (gid == 0) {
                    int jb = kk * 16 + tig * 2;
                    qpart[warp * 128 + jb]     = q0;
                    qpart[warp * 128 + jb + 1] = q1;
                    qpart[warp * 128 + jb + 8] = q2;
                    qpart[warp * 128 + jb + 9] = q3;
                }
            }
        }
    }

    if (last) {
        __syncthreads();
        if (tid < 128) {
            float qs = 0.f;
#pragma unroll
            for (int w = 0; w < 8; w++)
                qs += qpart[w * 128 + tid];
            qv[tid] = qs;
        }
        __syncthreads();
        // out[c] = sum_j q_j * H[j][c]  (+ 128*bias)
        {
            int c = tid >> 2, t4b = tid & 3;   // c: 0..63
            float a3 = 0.f;
#pragma unroll 8
            for (int jj = 0; jj < 32; jj++) {
                int j = t4b * 32 + jj;
                uint32_t byte = (uint32_t)(j * 128
                              + (((c >> 3) ^ (j & 7)) << 4) + (c & 7) * 2);
                a3 += qv[j] * __half2float(*(const __half*)(sm + OFF_U + byte));
            }
            a3 += __shfl_xor_sync(0xffffffffu, a3, 1);
            a3 += __shfl_xor_sync(0xffffffffu, a3, 2);
            if (t4b == 0)
                out_final[(size_t)b * 256 + gh * 64 + c] =
                    a3 + 128.f * biass[c];
        }
    }
}

// ---------------------------------------------------------------------------
extern "C" void kernel_launch(void* const* d_in, const int* in_sizes, int n_in,
                              void* d_out, int out_size)
{
    const float* x = (const float*)d_in[0];
    const float* W[3]    = {(const float*)d_in[2], (const float*)d_in[6],  (const float*)d_in[10]};
    const float* asv[3]  = {(const float*)d_in[3], (const float*)d_in[7],  (const float*)d_in[11]};
    const float* adv[3]  = {(const float*)d_in[4], (const float*)d_in[8],  (const float*)d_in[12]};
    const float* bias[3] = {(const float*)d_in[5], (const float*)d_in[9],  (const float*)d_in[13]};

    __half *pX, *pY, *pWt;
    cudaGetSymbolAddress((void**)&pX, g_X);
    cudaGetSymbolAddress((void**)&pY, g_Y);
    cudaGetSymbolAddress((void**)&pWt, g_Wt);

    cudaFuncSetAttribute(layer_kernel,
                         cudaFuncAttributeMaxDynamicSharedMemorySize, LAYER_SMEM);

    transpose_all_kernel<<<640, 256>>>(W[0], W[1], W[2], pWt);
    round_x_kernel<<<8192, 256>>>(x, pY);

    // layer 0: g_Y(xr) -> g_X ; layer 1: g_X -> g_Y ; layer 2: g_Y -> d_out
    const __half* in_buf[3]  = {pY, pX, pY};
    __half*       out_buf[3] = {pX, pY, nullptr};

    for (int l = 0; l < 3; l++) {
        const int K = (l == 0) ? 128 : 256;
        const __half* Wtl = pWt + (size_t)l * 65536;
        layer_kernel<<<dim3(B_GRAPHS, HEADS), 256, LAYER_SMEM>>>(
            in_buf[l], Wtl, asv[l], adv[l], bias[l],
            out_buf[l], (float*)d_out, K, l == 2);
    }
}